// round 1
// baseline (speedup 1.0000x reference)
#include <cuda_runtime.h>
#include <math.h>

#define H    4096
#define NH   32
#define HD   128
#define FF   11008
#define SEQ  1024
#define NL   2
#define OUT  512

// ---------------- scratch (static device globals; no runtime alloc) ----------
__device__ float g_h [SEQ * H];
__device__ float g_a [SEQ * H];
__device__ float g_q [SEQ * H];
__device__ float g_k [SEQ * H];
__device__ float g_v [SEQ * H];
__device__ float g_ao[SEQ * H];
__device__ float g_g [SEQ * FF];
__device__ float g_u [SEQ * FF];

// ---------------- embedding lookup ------------------------------------------
__global__ void embed_kernel(const int* __restrict__ x,
                             const float* __restrict__ embed,
                             float* __restrict__ h)
{
    int s   = blockIdx.x;
    int row = x[s];
    const float4* src = (const float4*)(embed + (size_t)row * H);
    float4*       dst = (float4*)(h + (size_t)s * H);
    for (int i = threadIdx.x; i < H / 4; i += blockDim.x) dst[i] = src[i];
}

// ---------------- rmsnorm ----------------------------------------------------
__global__ void __launch_bounds__(256)
rmsnorm_kernel(const float* __restrict__ x, const float* __restrict__ w,
               float* __restrict__ y)
{
    int row = blockIdx.x;
    const float* xr = x + (size_t)row * H;
    float ss = 0.f;
    for (int i = threadIdx.x * 4; i < H; i += 1024) {
        float4 v = *(const float4*)(xr + i);
        ss += v.x * v.x + v.y * v.y + v.z * v.z + v.w * v.w;
    }
    __shared__ float red[8];
    #pragma unroll
    for (int o = 16; o > 0; o >>= 1) ss += __shfl_xor_sync(0xffffffffu, ss, o);
    if ((threadIdx.x & 31) == 0) red[threadIdx.x >> 5] = ss;
    __syncthreads();
    float tot = 0.f;
    #pragma unroll
    for (int i = 0; i < 8; i++) tot += red[i];
    float r = rsqrtf(tot / (float)H + 1e-6f);
    for (int i = threadIdx.x * 4; i < H; i += 1024) {
        float4 v  = *(const float4*)(xr + i);
        float4 wv = *(const float4*)(w + i);
        float4 o  = make_float4(v.x * r * wv.x, v.y * r * wv.y,
                                v.z * r * wv.z, v.w * r * wv.w);
        *(float4*)(y + (size_t)row * H + i) = o;
    }
}

// ---------------- SGEMM: C[M,N] = A[M,K] @ B[K,N] (+Cin) (+bias row) --------
// 128x128 block tile, BK=16, 256 threads, 8x8 per thread. All dims multiples
// of tile sizes for this problem (M=1024; N in {512,4096,11008}; K in {4096,11008}).
__global__ void __launch_bounds__(256)
sgemm_kernel(int M, int N, int K,
             const float* __restrict__ A, const float* __restrict__ B,
             const float* __restrict__ Cin, const float* __restrict__ bias,
             float* __restrict__ C)
{
    __shared__ float As[16][128];
    __shared__ float Bs[16][128];
    const int tid = threadIdx.x;
    const int bx = blockIdx.x, by = blockIdx.y;
    const int tx = tid & 15, ty = tid >> 4;
    const int a_row = tid >> 2, a_col = (tid & 3) * 4;
    const int b_row = tid >> 5, b_col = (tid & 31) * 4;
    const float* Ab = A + (size_t)(by * 128) * K;
    const float* Bb = B + (size_t)(bx * 128);

    float acc[8][8];
    #pragma unroll
    for (int i = 0; i < 8; i++)
        #pragma unroll
        for (int j = 0; j < 8; j++) acc[i][j] = 0.f;

    for (int k0 = 0; k0 < K; k0 += 16) {
        #pragma unroll
        for (int i = 0; i < 2; i++) {
            int r = a_row + i * 64;
            float4 v4 = *(const float4*)(Ab + (size_t)r * K + k0 + a_col);
            As[a_col + 0][r] = v4.x; As[a_col + 1][r] = v4.y;
            As[a_col + 2][r] = v4.z; As[a_col + 3][r] = v4.w;
        }
        #pragma unroll
        for (int i = 0; i < 2; i++) {
            int r = b_row + i * 8;
            *(float4*)&Bs[r][b_col] =
                *(const float4*)(Bb + (size_t)(k0 + r) * N + b_col);
        }
        __syncthreads();
        #pragma unroll
        for (int kk = 0; kk < 16; kk++) {
            float af[8], bf[8];
            #pragma unroll
            for (int i = 0; i < 8; i++) af[i] = As[kk][ty * 8 + i];
            #pragma unroll
            for (int j = 0; j < 8; j++) bf[j] = Bs[kk][tx * 8 + j];
            #pragma unroll
            for (int i = 0; i < 8; i++)
                #pragma unroll
                for (int j = 0; j < 8; j++)
                    acc[i][j] = fmaf(af[i], bf[j], acc[i][j]);
        }
        __syncthreads();
    }

    #pragma unroll
    for (int i = 0; i < 8; i++) {
        int row = by * 128 + ty * 8 + i;
        #pragma unroll
        for (int j = 0; j < 8; j += 4) {
            int col = bx * 128 + tx * 8 + j;
            float4 v4 = make_float4(acc[i][j], acc[i][j + 1],
                                    acc[i][j + 2], acc[i][j + 3]);
            if (Cin) {
                float4 r4 = *(const float4*)(Cin + (size_t)row * N + col);
                v4.x += r4.x; v4.y += r4.y; v4.z += r4.z; v4.w += r4.w;
            }
            if (bias) {
                v4.x += bias[col]; v4.y += bias[col + 1];
                v4.z += bias[col + 2]; v4.w += bias[col + 3];
            }
            *(float4*)(C + (size_t)row * N + col) = v4;
        }
    }
}

// ---------------- RoPE (NeoX split-half), in place on q and k ---------------
__global__ void rope_kernel(float* __restrict__ q, float* __restrict__ k)
{
    int s = blockIdx.x;
    for (int idx = threadIdx.x; idx < NH * (HD / 2); idx += blockDim.x) {
        int hh = idx >> 6;
        int i  = idx & 63;
        float inv = (float)exp(-((double)(2 * i) / (double)HD) * log(10000.0));
        float fr  = (float)s * inv;
        float c = cosf(fr), sn = sinf(fr);
        size_t base = (size_t)s * H + hh * HD;
        float q1 = q[base + i], q2 = q[base + 64 + i];
        q[base + i]      = q1 * c - q2 * sn;
        q[base + 64 + i] = q2 * c + q1 * sn;
        float k1 = k[base + i], k2 = k[base + 64 + i];
        k[base + i]      = k1 * c - k2 * sn;
        k[base + 64 + i] = k2 * c + k1 * sn;
    }
}

// ---------------- causal attention, online softmax ---------------------------
// grid (SEQ, NH); 128 threads; thread t owns output dim t of this (q,head).
__global__ void __launch_bounds__(128)
attention_kernel(const float* __restrict__ Q, const float* __restrict__ K,
                 const float* __restrict__ V, float* __restrict__ Ot)
{
    const int qi = blockIdx.x, hh = blockIdx.y;
    const int t  = threadIdx.x;
    __shared__ float q_sh[HD];
    __shared__ float p_sh[128];
    __shared__ float redm[4], reds[4];

    q_sh[t] = Q[(size_t)qi * H + hh * HD + t];
    __syncthreads();

    const float scale = 0.08838834764831845f;  // 1/sqrt(128)
    float m_run = -1e30f, l_run = 0.f, o_acc = 0.f;
    const int nk = qi + 1;

    for (int kb = 0; kb < nk; kb += 128) {
        const int k = kb + t;
        float s = -1e30f;
        if (k < nk) {
            const float* kr = K + (size_t)k * H + hh * HD;
            float acc = 0.f;
            #pragma unroll
            for (int d = 0; d < HD; d += 4) {
                float4 kv = *(const float4*)(kr + d);
                acc = fmaf(kv.x, q_sh[d],     acc);
                acc = fmaf(kv.y, q_sh[d + 1], acc);
                acc = fmaf(kv.z, q_sh[d + 2], acc);
                acc = fmaf(kv.w, q_sh[d + 3], acc);
            }
            s = acc * scale;
        }
        // block-wide max
        float mx = s;
        #pragma unroll
        for (int o = 16; o > 0; o >>= 1)
            mx = fmaxf(mx, __shfl_xor_sync(0xffffffffu, mx, o));
        if ((t & 31) == 0) redm[t >> 5] = mx;
        __syncthreads();
        mx = fmaxf(fmaxf(redm[0], redm[1]), fmaxf(redm[2], redm[3]));
        float m_new = fmaxf(m_run, mx);

        float p = (k < nk) ? __expf(s - m_new) : 0.f;
        p_sh[t] = p;
        float ps = p;
        #pragma unroll
        for (int o = 16; o > 0; o >>= 1)
            ps += __shfl_xor_sync(0xffffffffu, ps, o);
        if ((t & 31) == 0) reds[t >> 5] = ps;
        __syncthreads();
        ps = reds[0] + reds[1] + reds[2] + reds[3];

        float corr = __expf(m_run - m_new);
        l_run = l_run * corr + ps;
        o_acc *= corr;

        const int kmax = min(128, nk - kb);
        const float* vb = V + (size_t)kb * H + hh * HD + t;
        for (int kk = 0; kk < kmax; kk++)
            o_acc = fmaf(p_sh[kk], vb[(size_t)kk * H], o_acc);

        m_run = m_new;
        __syncthreads();
    }
    Ot[(size_t)qi * H + hh * HD + t] = o_acc / l_run;
}

// ---------------- SwiGLU gate: g = silu(g) * u -------------------------------
__global__ void silu_mul_kernel(float* __restrict__ g,
                                const float* __restrict__ u, int n)
{
    int i = blockIdx.x * blockDim.x + threadIdx.x;
    if (i < n) {
        float x = g[i];
        float s = x / (1.f + __expf(-x));
        g[i] = s * u[i];
    }
}

// ---------------- launcher ---------------------------------------------------
extern "C" void kernel_launch(void* const* d_in, const int* in_sizes, int n_in,
                              void* d_out, int out_size)
{
    const int*   x     = (const int*)  d_in[0];
    const float* embed = (const float*)d_in[1];
    const float* Wq    = (const float*)d_in[2];
    const float* Wk    = (const float*)d_in[3];
    const float* Wv    = (const float*)d_in[4];
    const float* Wo    = (const float*)d_in[5];
    const float* Wg    = (const float*)d_in[6];
    const float* Wu    = (const float*)d_in[7];
    const float* Wd    = (const float*)d_in[8];
    const float* ln1   = (const float*)d_in[9];
    const float* ln2   = (const float*)d_in[10];
    const float* lnf   = (const float*)d_in[11];
    const float* Wout  = (const float*)d_in[12];
    const float* bout  = (const float*)d_in[13];
    float* out = (float*)d_out;

    float *h, *a, *q, *k, *v, *ao, *gg, *uu;
    cudaGetSymbolAddress((void**)&h,  g_h);
    cudaGetSymbolAddress((void**)&a,  g_a);
    cudaGetSymbolAddress((void**)&q,  g_q);
    cudaGetSymbolAddress((void**)&k,  g_k);
    cudaGetSymbolAddress((void**)&v,  g_v);
    cudaGetSymbolAddress((void**)&ao, g_ao);
    cudaGetSymbolAddress((void**)&gg, g_g);
    cudaGetSymbolAddress((void**)&uu, g_u);

    embed_kernel<<<SEQ, 256>>>(x, embed, h);

    dim3 grid_h(H / 128, SEQ / 128);
    dim3 grid_f(FF / 128, SEQ / 128);

    for (int l = 0; l < NL; l++) {
        const size_t wo_h = (size_t)l * H * H;
        const size_t wo_f = (size_t)l * H * FF;

        rmsnorm_kernel<<<SEQ, 256>>>(h, ln1 + (size_t)l * H, a);
        sgemm_kernel<<<grid_h, 256>>>(SEQ, H, H, a, Wq + wo_h, nullptr, nullptr, q);
        sgemm_kernel<<<grid_h, 256>>>(SEQ, H, H, a, Wk + wo_h, nullptr, nullptr, k);
        sgemm_kernel<<<grid_h, 256>>>(SEQ, H, H, a, Wv + wo_h, nullptr, nullptr, v);
        rope_kernel<<<SEQ, 256>>>(q, k);
        attention_kernel<<<dim3(SEQ, NH), 128>>>(q, k, v, ao);
        sgemm_kernel<<<grid_h, 256>>>(SEQ, H, H, ao, Wo + wo_h, h, nullptr, h);

        rmsnorm_kernel<<<SEQ, 256>>>(h, ln2 + (size_t)l * H, a);
        sgemm_kernel<<<grid_f, 256>>>(SEQ, FF, H, a, Wg + wo_f, nullptr, nullptr, gg);
        sgemm_kernel<<<grid_f, 256>>>(SEQ, FF, H, a, Wu + wo_f, nullptr, nullptr, uu);
        silu_mul_kernel<<<(SEQ * FF + 255) / 256, 256>>>(gg, uu, SEQ * FF);
        sgemm_kernel<<<grid_h, 256>>>(SEQ, H, FF, gg, Wd + (size_t)l * FF * H, h, nullptr, h);
    }

    rmsnorm_kernel<<<SEQ, 256>>>(h, lnf, a);
    sgemm_kernel<<<dim3(OUT / 128, SEQ / 128), 256>>>(SEQ, OUT, H, a, Wout,
                                                      nullptr, bout, out);
}

// round 4
// speedup vs baseline: 2.2455x; 2.2455x over previous
#include <cuda_runtime.h>
#include <cstdint>
#include <math.h>

#define H    4096
#define NH   32
#define HD   128
#define FF   11008
#define SEQ  1024
#define NL   2
#define OUT  512

// ---------------- scratch (static device globals; no runtime alloc) ----------
__device__ float g_h [SEQ * H];
__device__ float g_a [SEQ * H];
__device__ float g_q [SEQ * H];
__device__ float g_k [SEQ * H];
__device__ float g_v [SEQ * H];
__device__ float g_ao[SEQ * H];
__device__ float g_g [SEQ * FF];
__device__ float g_u [SEQ * FF];

// ---------------- helpers ----------------------------------------------------
__device__ __forceinline__ uint32_t smem_u32(const void* p) {
    uint32_t a;
    asm("{ .reg .u64 t; cvta.to.shared.u64 t, %1; cvt.u32.u64 %0, t; }"
        : "=r"(a) : "l"(p));
    return a;
}
__device__ __forceinline__ void cp16(uint32_t dst, const void* src) {
    asm volatile("cp.async.cg.shared.global [%0], [%1], 16;"
                 :: "r"(dst), "l"(src));
}
// split (f0,f1) into packed bf16x2 hi (leading 8 mantissa bits) and lo (next 8)
__device__ __forceinline__ void split2(float2 f, uint32_t& hi, uint32_t& lo) {
    asm("cvt.rn.bf16x2.f32 %0, %1, %2;" : "=r"(hi) : "f"(f.y), "f"(f.x));
    float h0 = __uint_as_float(hi << 16);
    float h1 = __uint_as_float(hi & 0xffff0000u);
    float r0 = f.x - h0;
    float r1 = f.y - h1;
    asm("cvt.rn.bf16x2.f32 %0, %1, %2;" : "=r"(lo) : "f"(r1), "f"(r0));
}
__device__ __forceinline__ void mma_bf16(float* d, const uint32_t* a,
                                         const uint32_t* b) {
    asm volatile(
        "mma.sync.aligned.m16n8k16.row.col.f32.bf16.bf16.f32 "
        "{%0,%1,%2,%3}, {%4,%5,%6,%7}, {%8,%9}, {%0,%1,%2,%3};"
        : "+f"(d[0]), "+f"(d[1]), "+f"(d[2]), "+f"(d[3])
        : "r"(a[0]), "r"(a[1]), "r"(a[2]), "r"(a[3]),
          "r"(b[0]), "r"(b[1]));
}

// SMEM: A buf = 128 rows x (32+4 pad) floats = 18432 B
//       B buf = 32 rows x (128+8 pad) floats = 17408 B
#define A_STRIDE 36
#define B_STRIDE 136
#define BUF_BYTES 35840        // one A buf + one B buf
#define GSM_BYTES (2 * BUF_BYTES)

// ---------------- bf16x2-split tensor-core GEMM: C = A@B (+Cin)(+bias) -------
// grid (N/128, M/128), 256 threads (8 warps, 2x4 warp grid, 64x32 warp tiles).
// Error-compensated: A,B split into bf16 hi/lo; D += Ah*Bh + Ah*Bl + Al*Bh.
__global__ void __launch_bounds__(256, 1)
tgemm_kernel(int M, int N, int K,
             const float* __restrict__ A, const float* __restrict__ B,
             const float* __restrict__ Cin, const float* __restrict__ bias,
             float* __restrict__ C)
{
    extern __shared__ char smem[];
    const uint32_t sb = smem_u32(smem);
    const int tid = threadIdx.x;
    const int wid = tid >> 5, lane = tid & 31;
    const int wrow = wid >> 2, wcol = wid & 3;
    const int gid = lane >> 2, tig = lane & 3;
    const int bx = blockIdx.x, by = blockIdx.y;

    const float* Ab = A + (size_t)by * 128 * K;
    const float* Bb = B + (size_t)bx * 128;
    const int NC = K >> 5;

    const int la_r  = tid >> 3, la_c4 = tid & 7;     // +32 rows per it
    const int lb_k  = tid >> 5, lb_n4 = tid & 31;    // +8 k per it

    auto issue = [&](int c, int b) {
        const float* Ac = Ab + c * 32;
        const float* Bc = Bb + (size_t)(c * 32) * N;
        uint32_t abase = sb + b * BUF_BYTES;
        uint32_t bbase = abase + 18432;
        #pragma unroll
        for (int it = 0; it < 4; it++) {
            int r = la_r + it * 32;
            cp16(abase + (uint32_t)(r * A_STRIDE + la_c4 * 4) * 4,
                 Ac + (size_t)r * K + la_c4 * 4);
        }
        #pragma unroll
        for (int it = 0; it < 4; it++) {
            int k = lb_k + it * 8;
            cp16(bbase + (uint32_t)(k * B_STRIDE + lb_n4 * 4) * 4,
                 Bc + (size_t)k * N + lb_n4 * 4);
        }
        asm volatile("cp.async.commit_group;" ::: "memory");
    };

    float acc[4][4][4];
    #pragma unroll
    for (int i = 0; i < 4; i++)
        #pragma unroll
        for (int j = 0; j < 4; j++)
            #pragma unroll
            for (int r = 0; r < 4; r++) acc[i][j][r] = 0.f;

    issue(0, 0);

    for (int c = 0; c < NC; c++) {
        const int b = c & 1;
        if (c + 1 < NC) {
            issue(c + 1, b ^ 1);
            asm volatile("cp.async.wait_group 1;" ::: "memory");
        } else {
            asm volatile("cp.async.wait_group 0;" ::: "memory");
        }
        __syncthreads();

        const float* As = (const float*)(smem + b * BUF_BYTES);
        const float* Bs = (const float*)(smem + b * BUF_BYTES + 18432);

        #pragma unroll
        for (int ks = 0; ks < 2; ks++) {
            const int kk = ks * 16 + tig * 2;
            uint32_t ah[4][4], al[4][4], bh[4][2], bl[4][2];
            #pragma unroll
            for (int im = 0; im < 4; im++) {
                const int m = wrow * 64 + im * 16 + gid;
                split2(*(const float2*)&As[m * A_STRIDE + kk],           ah[im][0], al[im][0]);
                split2(*(const float2*)&As[(m + 8) * A_STRIDE + kk],     ah[im][1], al[im][1]);
                split2(*(const float2*)&As[m * A_STRIDE + kk + 8],       ah[im][2], al[im][2]);
                split2(*(const float2*)&As[(m + 8) * A_STRIDE + kk + 8], ah[im][3], al[im][3]);
            }
            #pragma unroll
            for (int jn = 0; jn < 4; jn++) {
                const int n = wcol * 32 + jn * 8 + gid;
                float2 p0 = make_float2(Bs[kk * B_STRIDE + n],
                                        Bs[(kk + 1) * B_STRIDE + n]);
                float2 p1 = make_float2(Bs[(kk + 8) * B_STRIDE + n],
                                        Bs[(kk + 9) * B_STRIDE + n]);
                split2(p0, bh[jn][0], bl[jn][0]);
                split2(p1, bh[jn][1], bl[jn][1]);
            }
            #pragma unroll
            for (int im = 0; im < 4; im++)
                #pragma unroll
                for (int jn = 0; jn < 4; jn++) {
                    mma_bf16(acc[im][jn], ah[im], bl[jn]);
                    mma_bf16(acc[im][jn], al[im], bh[jn]);
                    mma_bf16(acc[im][jn], ah[im], bh[jn]);
                }
        }
        __syncthreads();
    }

    // epilogue
    #pragma unroll
    for (int im = 0; im < 4; im++) {
        const int row0 = by * 128 + wrow * 64 + im * 16 + gid;
        #pragma unroll
        for (int jn = 0; jn < 4; jn++) {
            const int col = bx * 128 + wcol * 32 + jn * 8 + tig * 2;
            float2 v0 = make_float2(acc[im][jn][0], acc[im][jn][1]);
            float2 v1 = make_float2(acc[im][jn][2], acc[im][jn][3]);
            if (Cin) {
                float2 r0 = *(const float2*)(Cin + (size_t)row0 * N + col);
                float2 r1 = *(const float2*)(Cin + (size_t)(row0 + 8) * N + col);
                v0.x += r0.x; v0.y += r0.y;
                v1.x += r1.x; v1.y += r1.y;
            }
            if (bias) {
                float b0 = bias[col], b1 = bias[col + 1];
                v0.x += b0; v0.y += b1;
                v1.x += b0; v1.y += b1;
            }
            *(float2*)(C + (size_t)row0 * N + col) = v0;
            *(float2*)(C + (size_t)(row0 + 8) * N + col) = v1;
        }
    }
}

// ---------------- embedding lookup ------------------------------------------
__global__ void embed_kernel(const int* __restrict__ x,
                             const float* __restrict__ embed,
                             float* __restrict__ h)
{
    int s   = blockIdx.x;
    int row = x[s];
    const float4* src = (const float4*)(embed + (size_t)row * H);
    float4*       dst = (float4*)(h + (size_t)s * H);
    for (int i = threadIdx.x; i < H / 4; i += blockDim.x) dst[i] = src[i];
}

// ---------------- rmsnorm ----------------------------------------------------
__global__ void __launch_bounds__(256)
rmsnorm_kernel(const float* __restrict__ x, const float* __restrict__ w,
               float* __restrict__ y)
{
    int row = blockIdx.x;
    const float* xr = x + (size_t)row * H;
    float ss = 0.f;
    for (int i = threadIdx.x * 4; i < H; i += 1024) {
        float4 v = *(const float4*)(xr + i);
        ss += v.x * v.x + v.y * v.y + v.z * v.z + v.w * v.w;
    }
    __shared__ float red[8];
    #pragma unroll
    for (int o = 16; o > 0; o >>= 1) ss += __shfl_xor_sync(0xffffffffu, ss, o);
    if ((threadIdx.x & 31) == 0) red[threadIdx.x >> 5] = ss;
    __syncthreads();
    float tot = 0.f;
    #pragma unroll
    for (int i = 0; i < 8; i++) tot += red[i];
    float r = rsqrtf(tot / (float)H + 1e-6f);
    for (int i = threadIdx.x * 4; i < H; i += 1024) {
        float4 v  = *(const float4*)(xr + i);
        float4 wv = *(const float4*)(w + i);
        float4 o  = make_float4(v.x * r * wv.x, v.y * r * wv.y,
                                v.z * r * wv.z, v.w * r * wv.w);
        *(float4*)(y + (size_t)row * H + i) = o;
    }
}

// ---------------- RoPE (NeoX split-half), in place on q and k ---------------
__global__ void rope_kernel(float* __restrict__ q, float* __restrict__ k)
{
    int s = blockIdx.x;
    for (int idx = threadIdx.x; idx < NH * (HD / 2); idx += blockDim.x) {
        int hh = idx >> 6;
        int i  = idx & 63;
        float inv = (float)exp(-((double)(2 * i) / (double)HD) * log(10000.0));
        float fr  = (float)s * inv;
        float c = cosf(fr), sn = sinf(fr);
        size_t base = (size_t)s * H + hh * HD;
        float q1 = q[base + i], q2 = q[base + 64 + i];
        q[base + i]      = q1 * c - q2 * sn;
        q[base + 64 + i] = q2 * c + q1 * sn;
        float k1 = k[base + i], k2 = k[base + 64 + i];
        k[base + i]      = k1 * c - k2 * sn;
        k[base + 64 + i] = k2 * c + k1 * sn;
    }
}

// ---------------- causal attention, 8 q-rows per block, online softmax -------
__global__ void __launch_bounds__(128)
attn8_kernel(const float* __restrict__ Q, const float* __restrict__ K,
             const float* __restrict__ V, float* __restrict__ Ot)
{
    const int qi0 = blockIdx.x * 8, hh = blockIdx.y;
    const int t = threadIdx.x, wq = t >> 5, lid = t & 31;
    __shared__ float q_sh[8][HD];
    __shared__ float p_sh[8][128];
    __shared__ float redm[8][4], reds[8][4];

    #pragma unroll
    for (int r = 0; r < 8; r++)
        q_sh[r][t] = Q[(size_t)(qi0 + r) * H + hh * HD + t];
    __syncthreads();

    const float scale = 0.08838834764831845f;
    float m_run[8], l_run[8], o_acc[8];
    #pragma unroll
    for (int r = 0; r < 8; r++) { m_run[r] = -1e30f; l_run[r] = 0.f; o_acc[r] = 0.f; }

    const int nkmax = qi0 + 8;
    for (int kb = 0; kb < nkmax; kb += 128) {
        const int k = kb + t;
        float s[8];
        const bool kin = (k < nkmax);
        #pragma unroll
        for (int r = 0; r < 8; r++) s[r] = 0.f;
        if (kin) {
            const float* kr = K + (size_t)k * H + hh * HD;
            #pragma unroll 8
            for (int d = 0; d < HD; d += 4) {
                float4 kv = *(const float4*)(kr + d);
                #pragma unroll
                for (int r = 0; r < 8; r++) {
                    s[r] = fmaf(kv.x, q_sh[r][d],     s[r]);
                    s[r] = fmaf(kv.y, q_sh[r][d + 1], s[r]);
                    s[r] = fmaf(kv.z, q_sh[r][d + 2], s[r]);
                    s[r] = fmaf(kv.w, q_sh[r][d + 3], s[r]);
                }
            }
        }
        #pragma unroll
        for (int r = 0; r < 8; r++)
            s[r] = (kin && k <= qi0 + r) ? s[r] * scale : -1e30f;

        float mx[8];
        #pragma unroll
        for (int r = 0; r < 8; r++) mx[r] = s[r];
        #pragma unroll
        for (int o = 16; o > 0; o >>= 1)
            #pragma unroll
            for (int r = 0; r < 8; r++)
                mx[r] = fmaxf(mx[r], __shfl_xor_sync(0xffffffffu, mx[r], o));
        if (lid == 0)
            #pragma unroll
            for (int r = 0; r < 8; r++) redm[r][wq] = mx[r];
        __syncthreads();

        float m_new[8], p[8];
        #pragma unroll
        for (int r = 0; r < 8; r++) {
            float bm = fmaxf(fmaxf(redm[r][0], redm[r][1]),
                             fmaxf(redm[r][2], redm[r][3]));
            m_new[r] = fmaxf(m_run[r], bm);
            p[r] = __expf(s[r] - m_new[r]);
            p_sh[r][t] = p[r];
        }
        #pragma unroll
        for (int o = 16; o > 0; o >>= 1)
            #pragma unroll
            for (int r = 0; r < 8; r++)
                p[r] += __shfl_xor_sync(0xffffffffu, p[r], o);
        if (lid == 0)
            #pragma unroll
            for (int r = 0; r < 8; r++) reds[r][wq] = p[r];
        __syncthreads();

        #pragma unroll
        for (int r = 0; r < 8; r++) {
            float ps = reds[r][0] + reds[r][1] + reds[r][2] + reds[r][3];
            float corr = __expf(m_run[r] - m_new[r]);
            l_run[r] = l_run[r] * corr + ps;
            o_acc[r] *= corr;
            m_run[r] = m_new[r];
        }

        const int kmax = min(128, nkmax - kb);
        const float* vb = V + (size_t)kb * H + hh * HD + t;
        for (int c4 = 0; c4 * 4 < kmax; c4++) {
            float pv[8][4];
            #pragma unroll
            for (int r = 0; r < 8; r++) {
                float4 p4 = *(const float4*)&p_sh[r][c4 * 4];
                pv[r][0] = p4.x; pv[r][1] = p4.y; pv[r][2] = p4.z; pv[r][3] = p4.w;
            }
            #pragma unroll
            for (int j = 0; j < 4; j++) {
                float v = vb[(size_t)(c4 * 4 + j) * H];
                #pragma unroll
                for (int r = 0; r < 8; r++)
                    o_acc[r] = fmaf(pv[r][j], v, o_acc[r]);
            }
        }
        __syncthreads();
    }
    #pragma unroll
    for (int r = 0; r < 8; r++)
        Ot[(size_t)(qi0 + r) * H + hh * HD + t] = o_acc[r] / l_run[r];
}

// ---------------- SwiGLU gate: g = silu(g) * u -------------------------------
__global__ void silu_mul_kernel(float* __restrict__ g,
                                const float* __restrict__ u, int n)
{
    int i = blockIdx.x * blockDim.x + threadIdx.x;
    if (i < n) {
        float x = g[i];
        float s = x / (1.f + __expf(-x));
        g[i] = s * u[i];
    }
}

// ---------------- launcher ---------------------------------------------------
extern "C" void kernel_launch(void* const* d_in, const int* in_sizes, int n_in,
                              void* d_out, int out_size)
{
    const int*   x     = (const int*)  d_in[0];
    const float* embed = (const float*)d_in[1];
    const float* Wq    = (const float*)d_in[2];
    const float* Wk    = (const float*)d_in[3];
    const float* Wv    = (const float*)d_in[4];
    const float* Wo    = (const float*)d_in[5];
    const float* Wg    = (const float*)d_in[6];
    const float* Wu    = (const float*)d_in[7];
    const float* Wd    = (const float*)d_in[8];
    const float* ln1   = (const float*)d_in[9];
    const float* ln2   = (const float*)d_in[10];
    const float* lnf   = (const float*)d_in[11];
    const float* Wout  = (const float*)d_in[12];
    const float* bout  = (const float*)d_in[13];
    float* out = (float*)d_out;

    float *h, *a, *q, *k, *v, *ao, *gg, *uu;
    cudaGetSymbolAddress((void**)&h,  g_h);
    cudaGetSymbolAddress((void**)&a,  g_a);
    cudaGetSymbolAddress((void**)&q,  g_q);
    cudaGetSymbolAddress((void**)&k,  g_k);
    cudaGetSymbolAddress((void**)&v,  g_v);
    cudaGetSymbolAddress((void**)&ao, g_ao);
    cudaGetSymbolAddress((void**)&gg, g_g);
    cudaGetSymbolAddress((void**)&uu, g_u);

    cudaFuncSetAttribute(tgemm_kernel,
                         cudaFuncAttributeMaxDynamicSharedMemorySize, GSM_BYTES);

    embed_kernel<<<SEQ, 256>>>(x, embed, h);

    dim3 grid_h(H / 128, SEQ / 128);
    dim3 grid_f(FF / 128, SEQ / 128);

    for (int l = 0; l < NL; l++) {
        const size_t wo_h = (size_t)l * H * H;
        const size_t wo_f = (size_t)l * H * FF;

        rmsnorm_kernel<<<SEQ, 256>>>(h, ln1 + (size_t)l * H, a);
        tgemm_kernel<<<grid_h, 256, GSM_BYTES>>>(SEQ, H, H, a, Wq + wo_h, nullptr, nullptr, q);
        tgemm_kernel<<<grid_h, 256, GSM_BYTES>>>(SEQ, H, H, a, Wk + wo_h, nullptr, nullptr, k);
        tgemm_kernel<<<grid_h, 256, GSM_BYTES>>>(SEQ, H, H, a, Wv + wo_h, nullptr, nullptr, v);
        rope_kernel<<<SEQ, 256>>>(q, k);
        attn8_kernel<<<dim3(SEQ / 8, NH), 128>>>(q, k, v, ao);
        tgemm_kernel<<<grid_h, 256, GSM_BYTES>>>(SEQ, H, H, ao, Wo + wo_h, h, nullptr, h);

        rmsnorm_kernel<<<SEQ, 256>>>(h, ln2 + (size_t)l * H, a);
        tgemm_kernel<<<grid_f, 256, GSM_BYTES>>>(SEQ, FF, H, a, Wg + wo_f, nullptr, nullptr, gg);
        tgemm_kernel<<<grid_f, 256, GSM_BYTES>>>(SEQ, FF, H, a, Wu + wo_f, nullptr, nullptr, uu);
        silu_mul_kernel<<<(SEQ * FF + 255) / 256, 256>>>(gg, uu, SEQ * FF);
        tgemm_kernel<<<grid_h, 256, GSM_BYTES>>>(SEQ, H, FF, gg, Wd + (size_t)l * FF * H, h, nullptr, h);
    }

    rmsnorm_kernel<<<SEQ, 256>>>(h, lnf, a);
    tgemm_kernel<<<dim3(OUT / 128, SEQ / 128), 256, GSM_BYTES>>>(SEQ, OUT, H, a, Wout,
                                                                 nullptr, bout, out);
}

// round 5
// speedup vs baseline: 3.0927x; 1.3773x over previous
#include <cuda_runtime.h>
#include <cstdint>
#include <math.h>

#define H    4096
#define NH   32
#define HD   128
#define FF   11008
#define SEQ  1024
#define NL   2
#define OUT  512

#define KB_H (H / 16)     // 256
#define KB_F (FF / 16)    // 688

// ---------------- scratch (static device globals; no runtime alloc) ----------
__device__ float g_h [SEQ * H];
__device__ float g_a [SEQ * H];
__device__ float g_q [SEQ * H];
__device__ float g_k [SEQ * H];
__device__ float g_v [SEQ * H];
__device__ float g_ao[SEQ * H];
__device__ float g_g [SEQ * FF];
__device__ float g_u [SEQ * FF];

// split activations (A-side), sized for the largest (K=FF)
__device__ uint4 g_a4[(size_t)2 * (SEQ / 16) * KB_F * 32];

// split weights (B-side), fragment-major uint2 {r0,r1}, h-major within layer slice
#define SWQ_L ((size_t)2 * (H  / 8) * KB_H * 32)
#define SWG_L ((size_t)2 * (FF / 8) * KB_H * 32)
#define SWD_L ((size_t)2 * (H  / 8) * KB_F * 32)
#define SWOUT ((size_t)2 * (OUT/ 8) * KB_H * 32)
__device__ uint2 g_wq[NL * SWQ_L];
__device__ uint2 g_wk[NL * SWQ_L];
__device__ uint2 g_wv[NL * SWQ_L];
__device__ uint2 g_wo[NL * SWQ_L];
__device__ uint2 g_wg[NL * SWG_L];
__device__ uint2 g_wu[NL * SWG_L];
__device__ uint2 g_wd[NL * SWD_L];
__device__ uint2 g_wout[SWOUT];

// ---------------- helpers ----------------------------------------------------
__device__ __forceinline__ uint32_t smem_u32(const void* p) {
    uint32_t a;
    asm("{ .reg .u64 t; cvta.to.shared.u64 t, %1; cvt.u32.u64 %0, t; }"
        : "=r"(a) : "l"(p));
    return a;
}
__device__ __forceinline__ void cp16(uint32_t dst, const void* src) {
    asm volatile("cp.async.cg.shared.global [%0], [%1], 16;"
                 :: "r"(dst), "l"(src));
}
// split (f0,f1) -> packed bf16x2 hi (low16 = f0) and lo (residuals)
__device__ __forceinline__ void split2(float2 f, uint32_t& hi, uint32_t& lo) {
    asm("cvt.rn.bf16x2.f32 %0, %1, %2;" : "=r"(hi) : "f"(f.y), "f"(f.x));
    float h0 = __uint_as_float(hi << 16);
    float h1 = __uint_as_float(hi & 0xffff0000u);
    float r0 = f.x - h0;
    float r1 = f.y - h1;
    asm("cvt.rn.bf16x2.f32 %0, %1, %2;" : "=r"(lo) : "f"(r1), "f"(r0));
}
__device__ __forceinline__ void mma_bf16(float* d, const uint32_t* a,
                                         const uint32_t* b) {
    asm volatile(
        "mma.sync.aligned.m16n8k16.row.col.f32.bf16.bf16.f32 "
        "{%0,%1,%2,%3}, {%4,%5,%6,%7}, {%8,%9}, {%0,%1,%2,%3};"
        : "+f"(d[0]), "+f"(d[1]), "+f"(d[2]), "+f"(d[3])
        : "r"(a[0]), "r"(a[1]), "r"(a[2]), "r"(a[3]),
          "r"(b[0]), "r"(b[1]));
}

// ---------------- convert A-side X[M][K] -> fragment-major uint4 -------------
// dst[h][mb][kb][lane] uint4 = {r0,r1,r2,r3}; grid (M/16, K/128), 256 thr.
__global__ void __launch_bounds__(256)
convA_kernel(const float* __restrict__ X, uint4* __restrict__ dst, int M, int K)
{
    __shared__ float Xs[16][132];
    const int mb = blockIdx.x, kc = blockIdx.y;
    const int tid = threadIdx.x;
    const int KB = K >> 4, MB = M >> 4;
    #pragma unroll
    for (int it = 0; it < 2; it++) {
        int f4 = it * 256 + tid;
        int r = f4 >> 5, c4 = f4 & 31;
        float4 v = *(const float4*)(X + (size_t)(mb * 16 + r) * K + kc * 128 + c4 * 4);
        Xs[r][c4 * 4 + 0] = v.x; Xs[r][c4 * 4 + 1] = v.y;
        Xs[r][c4 * 4 + 2] = v.z; Xs[r][c4 * 4 + 3] = v.w;
    }
    __syncthreads();
    #pragma unroll
    for (int it = 0; it < 2; it++) {
        int idx = it * 256 + tid;
        int l = idx & 31, kbl = (idx >> 5) & 7, h = idx >> 8;
        int gid = l >> 2, tig = l & 3;
        int c0 = kbl * 16 + tig * 2;
        float2 p00 = make_float2(Xs[gid][c0],         Xs[gid][c0 + 1]);
        float2 p10 = make_float2(Xs[gid + 8][c0],     Xs[gid + 8][c0 + 1]);
        float2 p01 = make_float2(Xs[gid][c0 + 8],     Xs[gid][c0 + 9]);
        float2 p11 = make_float2(Xs[gid + 8][c0 + 8], Xs[gid + 8][c0 + 9]);
        uint32_t h00, l00, h10, l10, h01, l01, h11, l11;
        split2(p00, h00, l00); split2(p10, h10, l10);
        split2(p01, h01, l01); split2(p11, h11, l11);
        uint4 o = h ? make_uint4(l00, l10, l01, l11)
                    : make_uint4(h00, h10, h01, h11);
        dst[(((size_t)h * MB + mb) * KB + kc * 8 + kbl) * 32 + l] = o;
    }
}

// ---------------- convert B-side W[K][N] -> fragment-major uint2 -------------
// dst[h][nb][kb][lane] uint2 = {r0,r1}; grid (K/16, N/128), 256 thr.
__global__ void __launch_bounds__(256)
convB_kernel(const float* __restrict__ W, uint2* __restrict__ dst, int K, int N)
{
    __shared__ float Ws[16][132];
    const int kb = blockIdx.x, nc = blockIdx.y;
    const int tid = threadIdx.x;
    const int KB = K >> 4, NB8 = N >> 3;
    #pragma unroll
    for (int it = 0; it < 2; it++) {
        int f4 = it * 256 + tid;
        int r = f4 >> 5, c4 = f4 & 31;
        float4 v = *(const float4*)(W + (size_t)(kb * 16 + r) * N + nc * 128 + c4 * 4);
        Ws[r][c4 * 4 + 0] = v.x; Ws[r][c4 * 4 + 1] = v.y;
        Ws[r][c4 * 4 + 2] = v.z; Ws[r][c4 * 4 + 3] = v.w;
    }
    __syncthreads();
    #pragma unroll
    for (int it = 0; it < 4; it++) {
        int idx = it * 256 + tid;
        int l = idx & 31, nbl = (idx >> 5) & 15, h = idx >> 9;
        int gid = l >> 2, tig = l & 3;
        int n = nbl * 8 + gid;
        float2 q0 = make_float2(Ws[2 * tig][n],     Ws[2 * tig + 1][n]);
        float2 q1 = make_float2(Ws[2 * tig + 8][n], Ws[2 * tig + 9][n]);
        uint32_t qh0, ql0, qh1, ql1;
        split2(q0, qh0, ql0); split2(q1, qh1, ql1);
        uint2 o = h ? make_uint2(ql0, ql1) : make_uint2(qh0, qh1);
        dst[(((size_t)h * NB8 + nc * 16 + nbl) * KB + kb) * 32 + l] = o;
    }
}

// ---------------- split-bf16 tensor-core GEMM on fragment-major data ---------
// C[M,N] = A@B (+Cin)(+bias). grid (N/128, M/128), 256 thr, 2 CTAs/SM.
// SMEM per buffer: A 16KB + B 16KB = 32KB; double buffered = 64KB.
#define BUF 32768
#define GSM2 (2 * BUF)
__global__ void __launch_bounds__(256, 2)
tgemm2_kernel(int M, int N, int K,
              const uint4* __restrict__ A4, const uint2* __restrict__ B2,
              const float* __restrict__ Cin, const float* __restrict__ bias,
              float* __restrict__ C)
{
    extern __shared__ char smem[];
    const uint32_t sb = smem_u32(smem);
    const int tid = threadIdx.x;
    const int wid = tid >> 5, lane = tid & 31;
    const int wrow = wid >> 2, wcol = wid & 3;
    const int gid = lane >> 2, tig = lane & 3;
    const int bx = blockIdx.x, by = blockIdx.y;

    const int KB = K >> 4;
    const size_t hA = (size_t)(M >> 4) * KB * 32;   // uint4 units
    const size_t hB = (size_t)(N >> 3) * KB * 32;   // uint2 units
    const int NC = K >> 5;

    auto issue = [&](int c, int b) {
        const int kb0 = c * 2;
        uint32_t dstA = sb + b * BUF;
        uint32_t dstB = dstA + 16384;
        #pragma unroll
        for (int it = 0; it < 4; it++) {
            int idx = it * 256 + tid;
            int l = idx & 31, kb = (idx >> 5) & 1, mb = (idx >> 6) & 7, h = idx >> 9;
            const uint4* src = A4 + (size_t)h * hA
                             + ((size_t)(by * 8 + mb) * KB + kb0 + kb) * 32 + l;
            cp16(dstA + idx * 16, src);
        }
        #pragma unroll
        for (int it = 0; it < 4; it++) {
            int idx = it * 256 + tid;
            int inner = idx & 15, tile = idx >> 4;
            int kb = tile & 1, nb = (tile >> 1) & 15, h = tile >> 5;
            const uint2* src = B2 + (size_t)h * hB
                             + ((size_t)(bx * 16 + nb) * KB + kb0 + kb) * 32 + inner * 2;
            cp16(dstB + idx * 16, src);
        }
        asm volatile("cp.async.commit_group;" ::: "memory");
    };

    float acc[4][4][4];
    #pragma unroll
    for (int i = 0; i < 4; i++)
        #pragma unroll
        for (int j = 0; j < 4; j++)
            #pragma unroll
            for (int r = 0; r < 4; r++) acc[i][j][r] = 0.f;

    issue(0, 0);

    for (int c = 0; c < NC; c++) {
        const int b = c & 1;
        if (c + 1 < NC) {
            issue(c + 1, b ^ 1);
            asm volatile("cp.async.wait_group 1;" ::: "memory");
        } else {
            asm volatile("cp.async.wait_group 0;" ::: "memory");
        }
        __syncthreads();

        const uint4* As4 = (const uint4*)(smem + b * BUF);           // [2][8][2][32]
        const uint2* Bs2 = (const uint2*)(smem + b * BUF + 16384);   // [2][16][2][32]

        #pragma unroll
        for (int ks = 0; ks < 2; ks++) {
            uint2 bh[4], bl[4];
            #pragma unroll
            for (int jn = 0; jn < 4; jn++) {
                int nb = wcol * 4 + jn;
                bh[jn] = Bs2[((0 * 16 + nb) * 2 + ks) * 32 + lane];
                bl[jn] = Bs2[((1 * 16 + nb) * 2 + ks) * 32 + lane];
            }
            #pragma unroll
            for (int im = 0; im < 4; im++) {
                int mb = wrow * 4 + im;
                uint4 ah = As4[((0 * 8 + mb) * 2 + ks) * 32 + lane];
                uint4 al = As4[((1 * 8 + mb) * 2 + ks) * 32 + lane];
                #pragma unroll
                for (int jn = 0; jn < 4; jn++) {
                    mma_bf16(acc[im][jn], (const uint32_t*)&ah, (const uint32_t*)&bl[jn]);
                    mma_bf16(acc[im][jn], (const uint32_t*)&al, (const uint32_t*)&bh[jn]);
                    mma_bf16(acc[im][jn], (const uint32_t*)&ah, (const uint32_t*)&bh[jn]);
                }
            }
        }
        __syncthreads();
    }

    // epilogue
    #pragma unroll
    for (int im = 0; im < 4; im++) {
        const int row0 = by * 128 + wrow * 64 + im * 16 + gid;
        #pragma unroll
        for (int jn = 0; jn < 4; jn++) {
            const int col = bx * 128 + (wcol * 4 + jn) * 8 + tig * 2;
            float2 v0 = make_float2(acc[im][jn][0], acc[im][jn][1]);
            float2 v1 = make_float2(acc[im][jn][2], acc[im][jn][3]);
            if (Cin) {
                float2 r0 = *(const float2*)(Cin + (size_t)row0 * N + col);
                float2 r1 = *(const float2*)(Cin + (size_t)(row0 + 8) * N + col);
                v0.x += r0.x; v0.y += r0.y;
                v1.x += r1.x; v1.y += r1.y;
            }
            if (bias) {
                float b0 = bias[col], b1 = bias[col + 1];
                v0.x += b0; v0.y += b1;
                v1.x += b0; v1.y += b1;
            }
            *(float2*)(C + (size_t)row0 * N + col) = v0;
            *(float2*)(C + (size_t)(row0 + 8) * N + col) = v1;
        }
    }
}

// ---------------- embedding lookup ------------------------------------------
__global__ void embed_kernel(const int* __restrict__ x,
                             const float* __restrict__ embed,
                             float* __restrict__ h)
{
    int s   = blockIdx.x;
    int row = x[s];
    const float4* src = (const float4*)(embed + (size_t)row * H);
    float4*       dst = (float4*)(h + (size_t)s * H);
    for (int i = threadIdx.x; i < H / 4; i += blockDim.x) dst[i] = src[i];
}

// ---------------- rmsnorm ----------------------------------------------------
__global__ void __launch_bounds__(256)
rmsnorm_kernel(const float* __restrict__ x, const float* __restrict__ w,
               float* __restrict__ y)
{
    int row = blockIdx.x;
    const float* xr = x + (size_t)row * H;
    float ss = 0.f;
    for (int i = threadIdx.x * 4; i < H; i += 1024) {
        float4 v = *(const float4*)(xr + i);
        ss += v.x * v.x + v.y * v.y + v.z * v.z + v.w * v.w;
    }
    __shared__ float red[8];
    #pragma unroll
    for (int o = 16; o > 0; o >>= 1) ss += __shfl_xor_sync(0xffffffffu, ss, o);
    if ((threadIdx.x & 31) == 0) red[threadIdx.x >> 5] = ss;
    __syncthreads();
    float tot = 0.f;
    #pragma unroll
    for (int i = 0; i < 8; i++) tot += red[i];
    float r = rsqrtf(tot / (float)H + 1e-6f);
    for (int i = threadIdx.x * 4; i < H; i += 1024) {
        float4 v  = *(const float4*)(xr + i);
        float4 wv = *(const float4*)(w + i);
        float4 o  = make_float4(v.x * r * wv.x, v.y * r * wv.y,
                                v.z * r * wv.z, v.w * r * wv.w);
        *(float4*)(y + (size_t)row * H + i) = o;
    }
}

// ---------------- RoPE (NeoX split-half), in place on q and k ---------------
__global__ void rope_kernel(float* __restrict__ q, float* __restrict__ k)
{
    int s = blockIdx.x;
    for (int idx = threadIdx.x; idx < NH * (HD / 2); idx += blockDim.x) {
        int hh = idx >> 6;
        int i  = idx & 63;
        float inv = (float)exp(-((double)(2 * i) / (double)HD) * log(10000.0));
        float fr  = (float)s * inv;
        float c = cosf(fr), sn = sinf(fr);
        size_t base = (size_t)s * H + hh * HD;
        float q1 = q[base + i], q2 = q[base + 64 + i];
        q[base + i]      = q1 * c - q2 * sn;
        q[base + 64 + i] = q2 * c + q1 * sn;
        float k1 = k[base + i], k2 = k[base + 64 + i];
        k[base + i]      = k1 * c - k2 * sn;
        k[base + 64 + i] = k2 * c + k1 * sn;
    }
}

// ---------------- causal attention, 8 q-rows per block, online softmax -------
__global__ void __launch_bounds__(128)
attn8_kernel(const float* __restrict__ Q, const float* __restrict__ K,
             const float* __restrict__ V, float* __restrict__ Ot)
{
    const int qi0 = blockIdx.x * 8, hh = blockIdx.y;
    const int t = threadIdx.x, wq = t >> 5, lid = t & 31;
    __shared__ float q_sh[8][HD];
    __shared__ float p_sh[8][128];
    __shared__ float redm[8][4], reds[8][4];

    #pragma unroll
    for (int r = 0; r < 8; r++)
        q_sh[r][t] = Q[(size_t)(qi0 + r) * H + hh * HD + t];
    __syncthreads();

    const float scale = 0.08838834764831845f;
    float m_run[8], l_run[8], o_acc[8];
    #pragma unroll
    for (int r = 0; r < 8; r++) { m_run[r] = -1e30f; l_run[r] = 0.f; o_acc[r] = 0.f; }

    const int nkmax = qi0 + 8;
    for (int kb = 0; kb < nkmax; kb += 128) {
        const int k = kb + t;
        float s[8];
        const bool kin = (k < nkmax);
        #pragma unroll
        for (int r = 0; r < 8; r++) s[r] = 0.f;
        if (kin) {
            const float* kr = K + (size_t)k * H + hh * HD;
            #pragma unroll 8
            for (int d = 0; d < HD; d += 4) {
                float4 kv = *(const float4*)(kr + d);
                #pragma unroll
                for (int r = 0; r < 8; r++) {
                    s[r] = fmaf(kv.x, q_sh[r][d],     s[r]);
                    s[r] = fmaf(kv.y, q_sh[r][d + 1], s[r]);
                    s[r] = fmaf(kv.z, q_sh[r][d + 2], s[r]);
                    s[r] = fmaf(kv.w, q_sh[r][d + 3], s[r]);
                }
            }
        }
        #pragma unroll
        for (int r = 0; r < 8; r++)
            s[r] = (kin && k <= qi0 + r) ? s[r] * scale : -1e30f;

        float mx[8];
        #pragma unroll
        for (int r = 0; r < 8; r++) mx[r] = s[r];
        #pragma unroll
        for (int o = 16; o > 0; o >>= 1)
            #pragma unroll
            for (int r = 0; r < 8; r++)
                mx[r] = fmaxf(mx[r], __shfl_xor_sync(0xffffffffu, mx[r], o));
        if (lid == 0)
            #pragma unroll
            for (int r = 0; r < 8; r++) redm[r][wq] = mx[r];
        __syncthreads();

        float m_new[8], p[8];
        #pragma unroll
        for (int r = 0; r < 8; r++) {
            float bm = fmaxf(fmaxf(redm[r][0], redm[r][1]),
                             fmaxf(redm[r][2], redm[r][3]));
            m_new[r] = fmaxf(m_run[r], bm);
            p[r] = __expf(s[r] - m_new[r]);
            p_sh[r][t] = p[r];
        }
        #pragma unroll
        for (int o = 16; o > 0; o >>= 1)
            #pragma unroll
            for (int r = 0; r < 8; r++)
                p[r] += __shfl_xor_sync(0xffffffffu, p[r], o);
        if (lid == 0)
            #pragma unroll
            for (int r = 0; r < 8; r++) reds[r][wq] = p[r];
        __syncthreads();

        #pragma unroll
        for (int r = 0; r < 8; r++) {
            float ps = reds[r][0] + reds[r][1] + reds[r][2] + reds[r][3];
            float corr = __expf(m_run[r] - m_new[r]);
            l_run[r] = l_run[r] * corr + ps;
            o_acc[r] *= corr;
            m_run[r] = m_new[r];
        }

        const int kmax = min(128, nkmax - kb);
        const float* vb = V + (size_t)kb * H + hh * HD + t;
        for (int c4 = 0; c4 * 4 < kmax; c4++) {
            float pv[8][4];
            #pragma unroll
            for (int r = 0; r < 8; r++) {
                float4 p4 = *(const float4*)&p_sh[r][c4 * 4];
                pv[r][0] = p4.x; pv[r][1] = p4.y; pv[r][2] = p4.z; pv[r][3] = p4.w;
            }
            #pragma unroll
            for (int j = 0; j < 4; j++) {
                float v = vb[(size_t)(c4 * 4 + j) * H];
                #pragma unroll
                for (int r = 0; r < 8; r++)
                    o_acc[r] = fmaf(pv[r][j], v, o_acc[r]);
            }
        }
        __syncthreads();
    }
    #pragma unroll
    for (int r = 0; r < 8; r++)
        Ot[(size_t)(qi0 + r) * H + hh * HD + t] = o_acc[r] / l_run[r];
}

// ---------------- SwiGLU gate: g = silu(g) * u -------------------------------
__global__ void silu_mul_kernel(float* __restrict__ g,
                                const float* __restrict__ u, int n)
{
    int i = blockIdx.x * blockDim.x + threadIdx.x;
    if (i < n) {
        float x = g[i];
        float s = x / (1.f + __expf(-x));
        g[i] = s * u[i];
    }
}

// ---------------- launcher ---------------------------------------------------
extern "C" void kernel_launch(void* const* d_in, const int* in_sizes, int n_in,
                              void* d_out, int out_size)
{
    const int*   x     = (const int*)  d_in[0];
    const float* embed = (const float*)d_in[1];
    const float* Wq    = (const float*)d_in[2];
    const float* Wk    = (const float*)d_in[3];
    const float* Wv    = (const float*)d_in[4];
    const float* Wo    = (const float*)d_in[5];
    const float* Wg    = (const float*)d_in[6];
    const float* Wu    = (const float*)d_in[7];
    const float* Wd    = (const float*)d_in[8];
    const float* ln1   = (const float*)d_in[9];
    const float* ln2   = (const float*)d_in[10];
    const float* lnf   = (const float*)d_in[11];
    const float* Wout  = (const float*)d_in[12];
    const float* bout  = (const float*)d_in[13];
    float* out = (float*)d_out;

    float *h, *a, *q, *k, *v, *ao, *gg, *uu;
    uint4* a4;
    uint2 *wq, *wk, *wv, *wo, *wg, *wu, *wd, *wout;
    cudaGetSymbolAddress((void**)&h,  g_h);
    cudaGetSymbolAddress((void**)&a,  g_a);
    cudaGetSymbolAddress((void**)&q,  g_q);
    cudaGetSymbolAddress((void**)&k,  g_k);
    cudaGetSymbolAddress((void**)&v,  g_v);
    cudaGetSymbolAddress((void**)&ao, g_ao);
    cudaGetSymbolAddress((void**)&gg, g_g);
    cudaGetSymbolAddress((void**)&uu, g_u);
    cudaGetSymbolAddress((void**)&a4, g_a4);
    cudaGetSymbolAddress((void**)&wq, g_wq);
    cudaGetSymbolAddress((void**)&wk, g_wk);
    cudaGetSymbolAddress((void**)&wv, g_wv);
    cudaGetSymbolAddress((void**)&wo, g_wo);
    cudaGetSymbolAddress((void**)&wg, g_wg);
    cudaGetSymbolAddress((void**)&wu, g_wu);
    cudaGetSymbolAddress((void**)&wd, g_wd);
    cudaGetSymbolAddress((void**)&wout, g_wout);

    cudaFuncSetAttribute(tgemm2_kernel,
                         cudaFuncAttributeMaxDynamicSharedMemorySize, GSM2);

    // ---- weight conversion (graph-captured; runs every launch) ----
    for (int l = 0; l < NL; l++) {
        convB_kernel<<<dim3(H / 16, H / 128), 256>>>(Wq + (size_t)l * H * H,  wq + l * SWQ_L, H, H);
        convB_kernel<<<dim3(H / 16, H / 128), 256>>>(Wk + (size_t)l * H * H,  wk + l * SWQ_L, H, H);
        convB_kernel<<<dim3(H / 16, H / 128), 256>>>(Wv + (size_t)l * H * H,  wv + l * SWQ_L, H, H);
        convB_kernel<<<dim3(H / 16, H / 128), 256>>>(Wo + (size_t)l * H * H,  wo + l * SWQ_L, H, H);
        convB_kernel<<<dim3(H / 16, FF / 128), 256>>>(Wg + (size_t)l * H * FF, wg + l * SWG_L, H, FF);
        convB_kernel<<<dim3(H / 16, FF / 128), 256>>>(Wu + (size_t)l * H * FF, wu + l * SWG_L, H, FF);
        convB_kernel<<<dim3(FF / 16, H / 128), 256>>>(Wd + (size_t)l * FF * H, wd + l * SWD_L, FF, H);
    }
    convB_kernel<<<dim3(H / 16, OUT / 128), 256>>>(Wout, wout, H, OUT);

    embed_kernel<<<SEQ, 256>>>(x, embed, h);

    dim3 grid_h(H / 128, SEQ / 128);
    dim3 grid_f(FF / 128, SEQ / 128);
    dim3 cvA_h(SEQ / 16, H / 128);
    dim3 cvA_f(SEQ / 16, FF / 128);

    for (int l = 0; l < NL; l++) {
        rmsnorm_kernel<<<SEQ, 256>>>(h, ln1 + (size_t)l * H, a);
        convA_kernel<<<cvA_h, 256>>>(a, a4, SEQ, H);
        tgemm2_kernel<<<grid_h, 256, GSM2>>>(SEQ, H, H, a4, wq + l * SWQ_L, nullptr, nullptr, q);
        tgemm2_kernel<<<grid_h, 256, GSM2>>>(SEQ, H, H, a4, wk + l * SWQ_L, nullptr, nullptr, k);
        tgemm2_kernel<<<grid_h, 256, GSM2>>>(SEQ, H, H, a4, wv + l * SWQ_L, nullptr, nullptr, v);
        rope_kernel<<<SEQ, 256>>>(q, k);
        attn8_kernel<<<dim3(SEQ / 8, NH), 128>>>(q, k, v, ao);
        convA_kernel<<<cvA_h, 256>>>(ao, a4, SEQ, H);
        tgemm2_kernel<<<grid_h, 256, GSM2>>>(SEQ, H, H, a4, wo + l * SWQ_L, h, nullptr, h);

        rmsnorm_kernel<<<SEQ, 256>>>(h, ln2 + (size_t)l * H, a);
        convA_kernel<<<cvA_h, 256>>>(a, a4, SEQ, H);
        tgemm2_kernel<<<grid_f, 256, GSM2>>>(SEQ, FF, H, a4, wg + l * SWG_L, nullptr, nullptr, gg);
        tgemm2_kernel<<<grid_f, 256, GSM2>>>(SEQ, FF, H, a4, wu + l * SWG_L, nullptr, nullptr, uu);
        silu_mul_kernel<<<(SEQ * FF + 255) / 256, 256>>>(gg, uu, SEQ * FF);
        convA_kernel<<<cvA_f, 256>>>(gg, a4, SEQ, FF);
        tgemm2_kernel<<<grid_h, 256, GSM2>>>(SEQ, H, FF, a4, wd + l * SWD_L, h, nullptr, h);
    }

    rmsnorm_kernel<<<SEQ, 256>>>(h, lnf, a);
    convA_kernel<<<cvA_h, 256>>>(a, a4, SEQ, H);
    tgemm2_kernel<<<dim3(OUT / 128, SEQ / 128), 256, GSM2>>>(SEQ, OUT, H, a4, wout,
                                                             nullptr, bout, out);
}

// round 6
// speedup vs baseline: 3.1881x; 1.0309x over previous
#include <cuda_runtime.h>
#include <cstdint>
#include <math.h>

#define H    4096
#define NH   32
#define HD   128
#define FF   11008
#define SEQ  1024
#define NL   2
#define OUT  512

#define KB_H (H / 16)     // 256
#define KB_F (FF / 16)    // 688

// ---------------- scratch (static device globals; no runtime alloc) ----------
__device__ float g_h  [SEQ * H];
__device__ float g_a  [SEQ * H];
__device__ float g_qkv[SEQ * 3 * H];
__device__ float g_ao [SEQ * H];
__device__ float g_g  [SEQ * FF];
__device__ float g_u  [SEQ * FF];

// split activations (A-side), sized for the largest (K=FF)
__device__ uint4 g_a4[(size_t)2 * (SEQ / 16) * KB_F * 32];

// split weights (B-side), fragment-major uint2 {r0,r1}
#define SWQ_L ((size_t)2 * (H  / 8) * KB_H * 32)
#define SWG_L ((size_t)2 * (FF / 8) * KB_H * 32)
#define SWD_L ((size_t)2 * (H  / 8) * KB_F * 32)
#define SWOUT ((size_t)2 * (OUT/ 8) * KB_H * 32)
#define SQKV_L ((size_t)2 * (3 * H / 8) * KB_H * 32)
__device__ uint2 g_wqkv[NL * SQKV_L];
__device__ uint2 g_wo[NL * SWQ_L];
__device__ uint2 g_wg[NL * SWG_L];
__device__ uint2 g_wu[NL * SWG_L];
__device__ uint2 g_wd[NL * SWD_L];
__device__ uint2 g_wout[SWOUT];

// ---------------- helpers ----------------------------------------------------
__device__ __forceinline__ uint32_t smem_u32(const void* p) {
    uint32_t a;
    asm("{ .reg .u64 t; cvta.to.shared.u64 t, %1; cvt.u32.u64 %0, t; }"
        : "=r"(a) : "l"(p));
    return a;
}
__device__ __forceinline__ void cp16(uint32_t dst, const void* src) {
    asm volatile("cp.async.cg.shared.global [%0], [%1], 16;"
                 :: "r"(dst), "l"(src));
}
// split (f0,f1) -> packed bf16x2 hi (low16 = f0) and lo (residuals)
__device__ __forceinline__ void split2(float2 f, uint32_t& hi, uint32_t& lo) {
    asm("cvt.rn.bf16x2.f32 %0, %1, %2;" : "=r"(hi) : "f"(f.y), "f"(f.x));
    float h0 = __uint_as_float(hi << 16);
    float h1 = __uint_as_float(hi & 0xffff0000u);
    float r0 = f.x - h0;
    float r1 = f.y - h1;
    asm("cvt.rn.bf16x2.f32 %0, %1, %2;" : "=r"(lo) : "f"(r1), "f"(r0));
}
__device__ __forceinline__ void mma_bf16(float* d, const uint32_t* a,
                                         const uint32_t* b) {
    asm volatile(
        "mma.sync.aligned.m16n8k16.row.col.f32.bf16.bf16.f32 "
        "{%0,%1,%2,%3}, {%4,%5,%6,%7}, {%8,%9}, {%0,%1,%2,%3};"
        : "+f"(d[0]), "+f"(d[1]), "+f"(d[2]), "+f"(d[3])
        : "r"(a[0]), "r"(a[1]), "r"(a[2]), "r"(a[3]),
          "r"(b[0]), "r"(b[1]));
}

// ---------------- convert A-side X[M][K] -> fragment-major uint4 -------------
__global__ void __launch_bounds__(256)
convA_kernel(const float* __restrict__ X, uint4* __restrict__ dst, int M, int K)
{
    __shared__ float Xs[16][132];
    const int mb = blockIdx.x, kc = blockIdx.y;
    const int tid = threadIdx.x;
    const int KB = K >> 4, MB = M >> 4;
    #pragma unroll
    for (int it = 0; it < 2; it++) {
        int f4 = it * 256 + tid;
        int r = f4 >> 5, c4 = f4 & 31;
        float4 v = *(const float4*)(X + (size_t)(mb * 16 + r) * K + kc * 128 + c4 * 4);
        Xs[r][c4 * 4 + 0] = v.x; Xs[r][c4 * 4 + 1] = v.y;
        Xs[r][c4 * 4 + 2] = v.z; Xs[r][c4 * 4 + 3] = v.w;
    }
    __syncthreads();
    #pragma unroll
    for (int it = 0; it < 2; it++) {
        int idx = it * 256 + tid;
        int l = idx & 31, kbl = (idx >> 5) & 7, h = idx >> 8;
        int gid = l >> 2, tig = l & 3;
        int c0 = kbl * 16 + tig * 2;
        float2 p00 = make_float2(Xs[gid][c0],         Xs[gid][c0 + 1]);
        float2 p10 = make_float2(Xs[gid + 8][c0],     Xs[gid + 8][c0 + 1]);
        float2 p01 = make_float2(Xs[gid][c0 + 8],     Xs[gid][c0 + 9]);
        float2 p11 = make_float2(Xs[gid + 8][c0 + 8], Xs[gid + 8][c0 + 9]);
        uint32_t h00, l00, h10, l10, h01, l01, h11, l11;
        split2(p00, h00, l00); split2(p10, h10, l10);
        split2(p01, h01, l01); split2(p11, h11, l11);
        uint4 o = h ? make_uint4(l00, l10, l01, l11)
                    : make_uint4(h00, h10, h01, h11);
        dst[(((size_t)h * MB + mb) * KB + kc * 8 + kbl) * 32 + l] = o;
    }
}

// ---------------- convert B-side W[K][N] -> fragment-major uint2 -------------
// reads W with row stride N; writes into dest tensor with NB8d 8-col blocks,
// at column-block offset nc_off (for packing multiple weights into one tensor).
__global__ void __launch_bounds__(256)
convB_kernel(const float* __restrict__ W, uint2* __restrict__ dst, int K, int N,
             int NB8d, int nc_off)
{
    __shared__ float Ws[16][132];
    const int kb = blockIdx.x, nc = blockIdx.y;
    const int tid = threadIdx.x;
    const int KB = K >> 4;
    #pragma unroll
    for (int it = 0; it < 2; it++) {
        int f4 = it * 256 + tid;
        int r = f4 >> 5, c4 = f4 & 31;
        float4 v = *(const float4*)(W + (size_t)(kb * 16 + r) * N + nc * 128 + c4 * 4);
        Ws[r][c4 * 4 + 0] = v.x; Ws[r][c4 * 4 + 1] = v.y;
        Ws[r][c4 * 4 + 2] = v.z; Ws[r][c4 * 4 + 3] = v.w;
    }
    __syncthreads();
    #pragma unroll
    for (int it = 0; it < 4; it++) {
        int idx = it * 256 + tid;
        int l = idx & 31, nbl = (idx >> 5) & 15, h = idx >> 9;
        int gid = l >> 2, tig = l & 3;
        int n = nbl * 8 + gid;
        float2 q0 = make_float2(Ws[2 * tig][n],     Ws[2 * tig + 1][n]);
        float2 q1 = make_float2(Ws[2 * tig + 8][n], Ws[2 * tig + 9][n]);
        uint32_t qh0, ql0, qh1, ql1;
        split2(q0, qh0, ql0); split2(q1, qh1, ql1);
        uint2 o = h ? make_uint2(ql0, ql1) : make_uint2(qh0, qh1);
        dst[(((size_t)h * NB8d + (nc_off + nc) * 16 + nbl) * KB + kb) * 32 + l] = o;
    }
}

// ---------------- split-bf16 tensor-core GEMM, 3-stage pipeline --------------
// C[M,N] = A@B (+Cin)(+bias). grid (N/128, M/128), 256 thr, 2 CTAs/SM.
#define BUF 32768
#define NST 3
#define GSM3 (NST * BUF)
__global__ void __launch_bounds__(256, 2)
tgemm2_kernel(int M, int N, int K,
              const uint4* __restrict__ A4, const uint2* __restrict__ B2,
              const float* __restrict__ Cin, const float* __restrict__ bias,
              float* __restrict__ C)
{
    extern __shared__ char smem[];
    const uint32_t sb = smem_u32(smem);
    const int tid = threadIdx.x;
    const int wid = tid >> 5, lane = tid & 31;
    const int wrow = wid >> 2, wcol = wid & 3;
    const int gid = lane >> 2, tig = lane & 3;
    const int bx = blockIdx.x, by = blockIdx.y;

    const int KB = K >> 4;
    const size_t hA = (size_t)(M >> 4) * KB * 32;   // uint4 units
    const size_t hB = (size_t)(N >> 3) * KB * 32;   // uint2 units
    const int NC = K >> 5;

    auto issue = [&](int c) {
        if (c < NC) {
            const int kb0 = c * 2;
            uint32_t dstA = sb + (uint32_t)(c % NST) * BUF;
            uint32_t dstB = dstA + 16384;
            #pragma unroll
            for (int it = 0; it < 4; it++) {
                int idx = it * 256 + tid;
                int l = idx & 31, kb = (idx >> 5) & 1, mb = (idx >> 6) & 7, h = idx >> 9;
                const uint4* src = A4 + (size_t)h * hA
                                 + ((size_t)(by * 8 + mb) * KB + kb0 + kb) * 32 + l;
                cp16(dstA + idx * 16, src);
            }
            #pragma unroll
            for (int it = 0; it < 4; it++) {
                int idx = it * 256 + tid;
                int inner = idx & 15, tile = idx >> 4;
                int kb = tile & 1, nb = (tile >> 1) & 15, h = tile >> 5;
                const uint2* src = B2 + (size_t)h * hB
                                 + ((size_t)(bx * 16 + nb) * KB + kb0 + kb) * 32 + inner * 2;
                cp16(dstB + idx * 16, src);
            }
        }
        asm volatile("cp.async.commit_group;" ::: "memory");
    };

    float acc[4][4][4];
    #pragma unroll
    for (int i = 0; i < 4; i++)
        #pragma unroll
        for (int j = 0; j < 4; j++)
            #pragma unroll
            for (int r = 0; r < 4; r++) acc[i][j][r] = 0.f;

    issue(0);
    issue(1);

    for (int c = 0; c < NC; c++) {
        // own group c done (pending <= {c+1}); barrier publishes all threads' data
        asm volatile("cp.async.wait_group 1;" ::: "memory");
        __syncthreads();
        issue(c + 2);   // overwrites buf (c-1)%3: safe, barrier proved compute(c-1) done

        const uint4* As4 = (const uint4*)(smem + (c % NST) * BUF);
        const uint2* Bs2 = (const uint2*)(smem + (c % NST) * BUF + 16384);

        #pragma unroll
        for (int ks = 0; ks < 2; ks++) {
            uint2 bh[4], bl[4];
            #pragma unroll
            for (int jn = 0; jn < 4; jn++) {
                int nb = wcol * 4 + jn;
                bh[jn] = Bs2[((0 * 16 + nb) * 2 + ks) * 32 + lane];
                bl[jn] = Bs2[((1 * 16 + nb) * 2 + ks) * 32 + lane];
            }
            #pragma unroll
            for (int im = 0; im < 4; im++) {
                int mb = wrow * 4 + im;
                uint4 ah = As4[((0 * 8 + mb) * 2 + ks) * 32 + lane];
                uint4 al = As4[((1 * 8 + mb) * 2 + ks) * 32 + lane];
                #pragma unroll
                for (int jn = 0; jn < 4; jn++) {
                    mma_bf16(acc[im][jn], (const uint32_t*)&ah, (const uint32_t*)&bl[jn]);
                    mma_bf16(acc[im][jn], (const uint32_t*)&al, (const uint32_t*)&bh[jn]);
                    mma_bf16(acc[im][jn], (const uint32_t*)&ah, (const uint32_t*)&bh[jn]);
                }
            }
        }
    }

    // epilogue
    #pragma unroll
    for (int im = 0; im < 4; im++) {
        const int row0 = by * 128 + wrow * 64 + im * 16 + gid;
        #pragma unroll
        for (int jn = 0; jn < 4; jn++) {
            const int col = bx * 128 + (wcol * 4 + jn) * 8 + tig * 2;
            float2 v0 = make_float2(acc[im][jn][0], acc[im][jn][1]);
            float2 v1 = make_float2(acc[im][jn][2], acc[im][jn][3]);
            if (Cin) {
                float2 r0 = *(const float2*)(Cin + (size_t)row0 * N + col);
                float2 r1 = *(const float2*)(Cin + (size_t)(row0 + 8) * N + col);
                v0.x += r0.x; v0.y += r0.y;
                v1.x += r1.x; v1.y += r1.y;
            }
            if (bias) {
                float b0 = bias[col], b1 = bias[col + 1];
                v0.x += b0; v0.y += b1;
                v1.x += b0; v1.y += b1;
            }
            *(float2*)(C + (size_t)row0 * N + col) = v0;
            *(float2*)(C + (size_t)(row0 + 8) * N + col) = v1;
        }
    }
}

// ---------------- embedding lookup ------------------------------------------
__global__ void embed_kernel(const int* __restrict__ x,
                             const float* __restrict__ embed,
                             float* __restrict__ h)
{
    int s   = blockIdx.x;
    int row = x[s];
    const float4* src = (const float4*)(embed + (size_t)row * H);
    float4*       dst = (float4*)(h + (size_t)s * H);
    for (int i = threadIdx.x; i < H / 4; i += blockDim.x) dst[i] = src[i];
}

// ---------------- rmsnorm ----------------------------------------------------
__global__ void __launch_bounds__(256)
rmsnorm_kernel(const float* __restrict__ x, const float* __restrict__ w,
               float* __restrict__ y)
{
    int row = blockIdx.x;
    const float* xr = x + (size_t)row * H;
    float ss = 0.f;
    for (int i = threadIdx.x * 4; i < H; i += 1024) {
        float4 v = *(const float4*)(xr + i);
        ss += v.x * v.x + v.y * v.y + v.z * v.z + v.w * v.w;
    }
    __shared__ float red[8];
    #pragma unroll
    for (int o = 16; o > 0; o >>= 1) ss += __shfl_xor_sync(0xffffffffu, ss, o);
    if ((threadIdx.x & 31) == 0) red[threadIdx.x >> 5] = ss;
    __syncthreads();
    float tot = 0.f;
    #pragma unroll
    for (int i = 0; i < 8; i++) tot += red[i];
    float r = rsqrtf(tot / (float)H + 1e-6f);
    for (int i = threadIdx.x * 4; i < H; i += 1024) {
        float4 v  = *(const float4*)(xr + i);
        float4 wv = *(const float4*)(w + i);
        float4 o  = make_float4(v.x * r * wv.x, v.y * r * wv.y,
                                v.z * r * wv.z, v.w * r * wv.w);
        *(float4*)(y + (size_t)row * H + i) = o;
    }
}

// ---------------- RoPE (NeoX split-half), in place; row stride ld ------------
__global__ void rope_kernel(float* __restrict__ q, float* __restrict__ k, int ld)
{
    int s = blockIdx.x;
    for (int idx = threadIdx.x; idx < NH * (HD / 2); idx += blockDim.x) {
        int hh = idx >> 6;
        int i  = idx & 63;
        float inv = (float)exp(-((double)(2 * i) / (double)HD) * log(10000.0));
        float fr  = (float)s * inv;
        float c = cosf(fr), sn = sinf(fr);
        size_t base = (size_t)s * ld + hh * HD;
        float q1 = q[base + i], q2 = q[base + 64 + i];
        q[base + i]      = q1 * c - q2 * sn;
        q[base + 64 + i] = q2 * c + q1 * sn;
        float k1 = k[base + i], k2 = k[base + 64 + i];
        k[base + i]      = k1 * c - k2 * sn;
        k[base + 64 + i] = k2 * c + k1 * sn;
    }
}

// ---------------- causal attention, 8 q-rows per block, online softmax -------
__global__ void __launch_bounds__(128)
attn8_kernel(const float* __restrict__ Q, const float* __restrict__ K,
             const float* __restrict__ V, float* __restrict__ Ot, int ld)
{
    const int qi0 = blockIdx.x * 8, hh = blockIdx.y;
    const int t = threadIdx.x, wq = t >> 5, lid = t & 31;
    __shared__ float q_sh[8][HD];
    __shared__ float p_sh[8][128];
    __shared__ float redm[8][4], reds[8][4];

    #pragma unroll
    for (int r = 0; r < 8; r++)
        q_sh[r][t] = Q[(size_t)(qi0 + r) * ld + hh * HD + t];
    __syncthreads();

    const float scale = 0.08838834764831845f;
    float m_run[8], l_run[8], o_acc[8];
    #pragma unroll
    for (int r = 0; r < 8; r++) { m_run[r] = -1e30f; l_run[r] = 0.f; o_acc[r] = 0.f; }

    const int nkmax = qi0 + 8;
    for (int kb = 0; kb < nkmax; kb += 128) {
        const int k = kb + t;
        float s[8];
        const bool kin = (k < nkmax);
        #pragma unroll
        for (int r = 0; r < 8; r++) s[r] = 0.f;
        if (kin) {
            const float* kr = K + (size_t)k * ld + hh * HD;
            #pragma unroll 8
            for (int d = 0; d < HD; d += 4) {
                float4 kv = *(const float4*)(kr + d);
                #pragma unroll
                for (int r = 0; r < 8; r++) {
                    s[r] = fmaf(kv.x, q_sh[r][d],     s[r]);
                    s[r] = fmaf(kv.y, q_sh[r][d + 1], s[r]);
                    s[r] = fmaf(kv.z, q_sh[r][d + 2], s[r]);
                    s[r] = fmaf(kv.w, q_sh[r][d + 3], s[r]);
                }
            }
        }
        #pragma unroll
        for (int r = 0; r < 8; r++)
            s[r] = (kin && k <= qi0 + r) ? s[r] * scale : -1e30f;

        float mx[8];
        #pragma unroll
        for (int r = 0; r < 8; r++) mx[r] = s[r];
        #pragma unroll
        for (int o = 16; o > 0; o >>= 1)
            #pragma unroll
            for (int r = 0; r < 8; r++)
                mx[r] = fmaxf(mx[r], __shfl_xor_sync(0xffffffffu, mx[r], o));
        if (lid == 0)
            #pragma unroll
            for (int r = 0; r < 8; r++) redm[r][wq] = mx[r];
        __syncthreads();

        float m_new[8], p[8];
        #pragma unroll
        for (int r = 0; r < 8; r++) {
            float bm = fmaxf(fmaxf(redm[r][0], redm[r][1]),
                             fmaxf(redm[r][2], redm[r][3]));
            m_new[r] = fmaxf(m_run[r], bm);
            p[r] = __expf(s[r] - m_new[r]);
            p_sh[r][t] = p[r];
        }
        #pragma unroll
        for (int o = 16; o > 0; o >>= 1)
            #pragma unroll
            for (int r = 0; r < 8; r++)
                p[r] += __shfl_xor_sync(0xffffffffu, p[r], o);
        if (lid == 0)
            #pragma unroll
            for (int r = 0; r < 8; r++) reds[r][wq] = p[r];
        __syncthreads();

        #pragma unroll
        for (int r = 0; r < 8; r++) {
            float ps = reds[r][0] + reds[r][1] + reds[r][2] + reds[r][3];
            float corr = __expf(m_run[r] - m_new[r]);
            l_run[r] = l_run[r] * corr + ps;
            o_acc[r] *= corr;
            m_run[r] = m_new[r];
        }

        const int kmax = min(128, nkmax - kb);
        const float* vb = V + (size_t)kb * ld + hh * HD + t;
        for (int c4 = 0; c4 * 4 < kmax; c4++) {
            float pv[8][4];
            #pragma unroll
            for (int r = 0; r < 8; r++) {
                float4 p4 = *(const float4*)&p_sh[r][c4 * 4];
                pv[r][0] = p4.x; pv[r][1] = p4.y; pv[r][2] = p4.z; pv[r][3] = p4.w;
            }
            #pragma unroll
            for (int j = 0; j < 4; j++) {
                float v = vb[(size_t)(c4 * 4 + j) * ld];
                #pragma unroll
                for (int r = 0; r < 8; r++)
                    o_acc[r] = fmaf(pv[r][j], v, o_acc[r]);
            }
        }
        __syncthreads();
    }
    #pragma unroll
    for (int r = 0; r < 8; r++)
        Ot[(size_t)(qi0 + r) * H + hh * HD + t] = o_acc[r] / l_run[r];
}

// ---------------- SwiGLU gate: g = silu(g) * u -------------------------------
__global__ void silu_mul_kernel(float* __restrict__ g,
                                const float* __restrict__ u, int n)
{
    int i = blockIdx.x * blockDim.x + threadIdx.x;
    if (i < n) {
        float x = g[i];
        float s = x / (1.f + __expf(-x));
        g[i] = s * u[i];
    }
}

// ---------------- launcher ---------------------------------------------------
extern "C" void kernel_launch(void* const* d_in, const int* in_sizes, int n_in,
                              void* d_out, int out_size)
{
    const int*   x     = (const int*)  d_in[0];
    const float* embed = (const float*)d_in[1];
    const float* Wq    = (const float*)d_in[2];
    const float* Wk    = (const float*)d_in[3];
    const float* Wv    = (const float*)d_in[4];
    const float* Wo    = (const float*)d_in[5];
    const float* Wg    = (const float*)d_in[6];
    const float* Wu    = (const float*)d_in[7];
    const float* Wd    = (const float*)d_in[8];
    const float* ln1   = (const float*)d_in[9];
    const float* ln2   = (const float*)d_in[10];
    const float* lnf   = (const float*)d_in[11];
    const float* Wout  = (const float*)d_in[12];
    const float* bout  = (const float*)d_in[13];
    float* out = (float*)d_out;

    float *h, *a, *qkv, *ao, *gg, *uu;
    uint4* a4;
    uint2 *wqkv, *wo, *wg, *wu, *wd, *wout;
    cudaGetSymbolAddress((void**)&h,   g_h);
    cudaGetSymbolAddress((void**)&a,   g_a);
    cudaGetSymbolAddress((void**)&qkv, g_qkv);
    cudaGetSymbolAddress((void**)&ao,  g_ao);
    cudaGetSymbolAddress((void**)&gg,  g_g);
    cudaGetSymbolAddress((void**)&uu,  g_u);
    cudaGetSymbolAddress((void**)&a4,  g_a4);
    cudaGetSymbolAddress((void**)&wqkv, g_wqkv);
    cudaGetSymbolAddress((void**)&wo,  g_wo);
    cudaGetSymbolAddress((void**)&wg,  g_wg);
    cudaGetSymbolAddress((void**)&wu,  g_wu);
    cudaGetSymbolAddress((void**)&wd,  g_wd);
    cudaGetSymbolAddress((void**)&wout, g_wout);

    cudaFuncSetAttribute(tgemm2_kernel,
                         cudaFuncAttributeMaxDynamicSharedMemorySize, GSM3);

    // ---- weight conversion (graph-captured; runs every launch) ----
    for (int l = 0; l < NL; l++) {
        uint2* wqkv_l = wqkv + l * SQKV_L;
        convB_kernel<<<dim3(H / 16, H / 128), 256>>>(Wq + (size_t)l * H * H, wqkv_l, H, H, 3 * H / 8, 0);
        convB_kernel<<<dim3(H / 16, H / 128), 256>>>(Wk + (size_t)l * H * H, wqkv_l, H, H, 3 * H / 8, 32);
        convB_kernel<<<dim3(H / 16, H / 128), 256>>>(Wv + (size_t)l * H * H, wqkv_l, H, H, 3 * H / 8, 64);
        convB_kernel<<<dim3(H / 16, H / 128), 256>>>(Wo + (size_t)l * H * H, wo + l * SWQ_L, H, H, H / 8, 0);
        convB_kernel<<<dim3(H / 16, FF / 128), 256>>>(Wg + (size_t)l * H * FF, wg + l * SWG_L, H, FF, FF / 8, 0);
        convB_kernel<<<dim3(H / 16, FF / 128), 256>>>(Wu + (size_t)l * H * FF, wu + l * SWG_L, H, FF, FF / 8, 0);
        convB_kernel<<<dim3(FF / 16, H / 128), 256>>>(Wd + (size_t)l * FF * H, wd + l * SWD_L, FF, H, H / 8, 0);
    }
    convB_kernel<<<dim3(H / 16, OUT / 128), 256>>>(Wout, wout, H, OUT, OUT / 8, 0);

    embed_kernel<<<SEQ, 256>>>(x, embed, h);

    dim3 grid_h(H / 128, SEQ / 128);
    dim3 grid_qkv(3 * H / 128, SEQ / 128);
    dim3 grid_f(FF / 128, SEQ / 128);
    dim3 cvA_h(SEQ / 16, H / 128);
    dim3 cvA_f(SEQ / 16, FF / 128);

    for (int l = 0; l < NL; l++) {
        rmsnorm_kernel<<<SEQ, 256>>>(h, ln1 + (size_t)l * H, a);
        convA_kernel<<<cvA_h, 256>>>(a, a4, SEQ, H);
        tgemm2_kernel<<<grid_qkv, 256, GSM3>>>(SEQ, 3 * H, H, a4, wqkv + l * SQKV_L,
                                               nullptr, nullptr, qkv);
        rope_kernel<<<SEQ, 256>>>(qkv, qkv + H, 3 * H);
        attn8_kernel<<<dim3(SEQ / 8, NH), 128>>>(qkv, qkv + H, qkv + 2 * H, ao, 3 * H);
        convA_kernel<<<cvA_h, 256>>>(ao, a4, SEQ, H);
        tgemm2_kernel<<<grid_h, 256, GSM3>>>(SEQ, H, H, a4, wo + l * SWQ_L, h, nullptr, h);

        rmsnorm_kernel<<<SEQ, 256>>>(h, ln2 + (size_t)l * H, a);
        convA_kernel<<<cvA_h, 256>>>(a, a4, SEQ, H);
        tgemm2_kernel<<<grid_f, 256, GSM3>>>(SEQ, FF, H, a4, wg + l * SWG_L, nullptr, nullptr, gg);
        tgemm2_kernel<<<grid_f, 256, GSM3>>>(SEQ, FF, H, a4, wu + l * SWG_L, nullptr, nullptr, uu);
        silu_mul_kernel<<<(SEQ * FF + 255) / 256, 256>>>(gg, uu, SEQ * FF);
        convA_kernel<<<cvA_f, 256>>>(gg, a4, SEQ, FF);
        tgemm2_kernel<<<grid_h, 256, GSM3>>>(SEQ, H, FF, a4, wd + l * SWD_L, h, nullptr, h);
    }

    rmsnorm_kernel<<<SEQ, 256>>>(h, lnf, a);
    convA_kernel<<<cvA_h, 256>>>(a, a4, SEQ, H);
    tgemm2_kernel<<<dim3(OUT / 128, SEQ / 128), 256, GSM3>>>(SEQ, OUT, H, a4, wout,
                                                             nullptr, bout, out);
}